// round 2
// baseline (speedup 1.0000x reference)
#include <cuda_runtime.h>

#define GG 512            // B*T graphs
#define NN 500            // nodes
#define FIN 96
#define HID 64
#define OUTF 96
#define ROWS (GG*NN)      // 256000
#define BN_EPS 1e-5f
#define NNZ_MAX (NN*NN)

// ---------------- scratch (device globals; no allocation allowed) ----------------
__device__ float g_t[(long)ROWS*HID];    // GEMM output / SpMM input
__device__ float g_s[(long)ROWS*HID];    // SpMM output
__device__ float g_h[(long)ROWS*HID];    // layer activations
__device__ float g_r[(long)ROWS*HID];    // layer-0 residual (x @ w_r0 + b_r0)
__device__ float g_dinv[NN];
__device__ int   g_cnt[NN];
__device__ int   g_rowptr[NN+1];
__device__ int   g_cols[NNZ_MAX];
__device__ float g_vals[NNZ_MAX];
__device__ float g_sum[HID];
__device__ float g_sumsq[HID];
__device__ float g_scale[HID];
__device__ float g_shift[HID];

// ---------------- prep: degrees / dinv + per-row nnz counts ----------------
__global__ void prep_deg(const float* __restrict__ adj) {
    int m = blockIdx.x;
    int tid = threadIdx.x;
    float sum = 0.f; int cnt = 0;
    for (int n = tid; n < NN; n += blockDim.x) {
        float a = adj[m*NN + n];
        sum += a;
        cnt += (a != 0.f) ? 1 : 0;
    }
    __shared__ float ssum[4]; __shared__ int scnt[4];
    #pragma unroll
    for (int o = 16; o; o >>= 1) {
        sum += __shfl_down_sync(0xFFFFFFFFu, sum, o);
        cnt += __shfl_down_sync(0xFFFFFFFFu, cnt, o);
    }
    int w = tid >> 5;
    if ((tid & 31) == 0) { ssum[w] = sum; scnt[w] = cnt; }
    __syncthreads();
    if (tid == 0) {
        float s = ssum[0] + ssum[1] + ssum[2] + ssum[3];
        int c = scnt[0] + scnt[1] + scnt[2] + scnt[3];
        // adjacency symmetric -> column sum == row sum; +1 self loop
        g_dinv[m] = rsqrtf(1.f + s);
        g_cnt[m] = c + 1;   // + diagonal
    }
    // re-zero BN accumulators at start of every launch (idempotent launches)
    if (blockIdx.x == 0 && tid < HID) { g_sum[tid] = 0.f; g_sumsq[tid] = 0.f; }
}

// exclusive scan of row counts -> rowptr (single block)
__global__ void prep_scan() {
    __shared__ int sc[512];
    int tid = threadIdx.x;
    sc[tid] = (tid < NN) ? g_cnt[tid] : 0;
    __syncthreads();
    for (int off = 1; off < 512; off <<= 1) {
        int v = (tid >= off) ? sc[tid - off] : 0;
        __syncthreads();
        sc[tid] += v;
        __syncthreads();
    }
    if (tid < NN) g_rowptr[tid + 1] = sc[tid];
    if (tid == 0) g_rowptr[0] = 0;
}

// fill CSR with normalized values: a_hat[m,n] = dinv[m]*a1[m,n]*dinv[n]
// DETERMINISTIC: one thread per row, columns scanned in ascending order,
// self-loop inserted at its sorted position (n == m). No atomics -> identical
// CSR (and identical fp accumulation order downstream) on every launch.
__global__ void prep_fill(const float* __restrict__ adj) {
    int m = blockIdx.x * blockDim.x + threadIdx.x;
    if (m >= NN) return;
    float dm = g_dinv[m];
    int p = g_rowptr[m];
    for (int n = 0; n < NN; n++) {
        if (n == m) {                 // self loop (adjacency diag is 0)
            g_cols[p] = m;
            g_vals[p] = dm * dm;
            p++;
        } else {
            float a = adj[m*NN + n];
            if (a != 0.f) {
                g_cols[p] = n;
                g_vals[p] = dm * a * g_dinv[n];
                p++;
            }
        }
    }
}

// ---------------- GEMM: C[row,c] = sum_f A[row,f]*B[f,c] + bias[c] ----------------
// 64x64 block tile, 128 threads, 4x8 per-thread tile, K chunked by 32.
template<int K, int C, bool ACCUM>
__global__ __launch_bounds__(128) void gemm_kernel(
    const float* __restrict__ A, const float* __restrict__ Bw,
    const float* __restrict__ bias, float* __restrict__ Cout)
{
    __shared__ float As[32][68];   // [f][row], padded (68*4B keeps 16B alignment)
    __shared__ float Bs[32][64];   // [f][col]
    int tid = threadIdx.x;
    long row0 = (long)blockIdx.x * 64;
    int col0 = blockIdx.y * 64;
    int tr = (tid >> 3) * 4;
    int tc = (tid & 7) * 8;
    float acc[4][8] = {};
    for (int k0 = 0; k0 < K; k0 += 32) {
        #pragma unroll
        for (int i = 0; i < 4; i++) {
            int s = tid + i * 128;       // 512 float4 slots = 64 rows x 32 f
            int r = s >> 3;
            int fq = s & 7;
            float4 v = *(const float4*)(A + (row0 + r) * K + (k0 + fq * 4));
            As[fq*4+0][r] = v.x; As[fq*4+1][r] = v.y;
            As[fq*4+2][r] = v.z; As[fq*4+3][r] = v.w;
        }
        #pragma unroll
        for (int i = 0; i < 4; i++) {
            int s = tid + i * 128;       // 512 float4 slots = 32 f x 64 c
            int f = s >> 4;
            int cq = s & 15;
            int c = col0 + cq * 4;
            float4 v = make_float4(0.f, 0.f, 0.f, 0.f);
            if ((C & 63) == 0 || c < C)
                v = *(const float4*)(Bw + (k0 + f) * C + c);
            Bs[f][cq*4+0] = v.x; Bs[f][cq*4+1] = v.y;
            Bs[f][cq*4+2] = v.z; Bs[f][cq*4+3] = v.w;
        }
        __syncthreads();
        #pragma unroll
        for (int f = 0; f < 32; f++) {
            float4 a4 = *(const float4*)&As[f][tr];
            float4 b0 = *(const float4*)&Bs[f][tc];
            float4 b1 = *(const float4*)&Bs[f][tc + 4];
            float av[4] = {a4.x, a4.y, a4.z, a4.w};
            float bv[8] = {b0.x, b0.y, b0.z, b0.w, b1.x, b1.y, b1.z, b1.w};
            #pragma unroll
            for (int i = 0; i < 4; i++)
                #pragma unroll
                for (int j = 0; j < 8; j++)
                    acc[i][j] += av[i] * bv[j];
        }
        __syncthreads();
    }
    #pragma unroll
    for (int i = 0; i < 4; i++) {
        long row = row0 + tr + i;
        float* dst = Cout + row * C + col0 + tc;
        #pragma unroll
        for (int j = 0; j < 8; j++) {
            int c = col0 + tc + j;
            if ((C & 63) == 0 || c < C) {
                float v = acc[i][j] + bias[c];
                if (ACCUM) v += dst[j];
                dst[j] = v;
            }
        }
    }
}

// ---------------- SpMM (s = a_hat @ t per graph) + BN stats partials ----------------
// blockDim (16,16): x*4 = channel (float4), y = row lane; block covers 125 rows of one graph.
__global__ __launch_bounds__(256) void spmm_stats(
    const float* __restrict__ T, float* __restrict__ S)
{
    int g = blockIdx.y;
    int m0 = blockIdx.x * 125;
    int cx = threadIdx.x;
    int c4 = cx * 4;
    int yr = threadIdx.y;
    const float* tg = T + (long)g * NN * HID;
    float* sg = S + (long)g * NN * HID;
    float lsum[4] = {0,0,0,0}, lsq[4] = {0,0,0,0};

    for (int m = m0 + yr; m < m0 + 125; m += 16) {
        int jb = g_rowptr[m], je = g_rowptr[m + 1];
        float4 acc = make_float4(0.f, 0.f, 0.f, 0.f);
        int j = jb;
        for (; j + 1 < je; j += 2) {
            int col0 = g_cols[j];     float w0 = g_vals[j];
            int col1 = g_cols[j + 1]; float w1 = g_vals[j + 1];
            float4 t0 = *(const float4*)(tg + col0 * HID + c4);
            float4 t1 = *(const float4*)(tg + col1 * HID + c4);
            acc.x += w0 * t0.x + w1 * t1.x;
            acc.y += w0 * t0.y + w1 * t1.y;
            acc.z += w0 * t0.z + w1 * t1.z;
            acc.w += w0 * t0.w + w1 * t1.w;
        }
        if (j < je) {
            int col = g_cols[j]; float w = g_vals[j];
            float4 tv = *(const float4*)(tg + col * HID + c4);
            acc.x += w * tv.x; acc.y += w * tv.y;
            acc.z += w * tv.z; acc.w += w * tv.w;
        }
        *(float4*)(sg + m * HID + c4) = acc;
        lsum[0] += acc.x; lsum[1] += acc.y; lsum[2] += acc.z; lsum[3] += acc.w;
        lsq[0] += acc.x * acc.x; lsq[1] += acc.y * acc.y;
        lsq[2] += acc.z * acc.z; lsq[3] += acc.w * acc.w;
    }

    __shared__ float red[16][64];
    // sum
    #pragma unroll
    for (int k = 0; k < 4; k++) red[yr][c4 + k] = lsum[k];
    __syncthreads();
    for (int off = 8; off >= 1; off >>= 1) {
        if (yr < off)
            #pragma unroll
            for (int k = 0; k < 4; k++) red[yr][c4 + k] += red[yr + off][c4 + k];
        __syncthreads();
    }
    if (yr == 0)
        #pragma unroll
        for (int k = 0; k < 4; k++) atomicAdd(&g_sum[c4 + k], red[0][c4 + k]);
    __syncthreads();
    // sumsq
    #pragma unroll
    for (int k = 0; k < 4; k++) red[yr][c4 + k] = lsq[k];
    __syncthreads();
    for (int off = 8; off >= 1; off >>= 1) {
        if (yr < off)
            #pragma unroll
            for (int k = 0; k < 4; k++) red[yr][c4 + k] += red[yr + off][c4 + k];
        __syncthreads();
    }
    if (yr == 0)
        #pragma unroll
        for (int k = 0; k < 4; k++) atomicAdd(&g_sumsq[c4 + k], red[0][c4 + k]);
}

// ---------------- BN finalize: fold (mean,var,gamma,beta) -> scale/shift; rezero accums ----
__global__ void bn_finalize(const float* __restrict__ gamma, const float* __restrict__ beta) {
    int c = threadIdx.x;
    float s = g_sum[c], q = g_sumsq[c];
    const float inv = 1.f / (float)ROWS;
    float mean = s * inv;
    float var = q * inv - mean * mean;
    float rstd = rsqrtf(var + BN_EPS);
    float a = rstd * gamma[c];
    g_scale[c] = a;
    g_shift[c] = beta[c] - mean * a;
    g_sum[c] = 0.f; g_sumsq[c] = 0.f;
}

// ---------------- normalize + relu + residual ----------------
__global__ __launch_bounds__(256) void norm_relu_res(
    const float* __restrict__ S, const float* __restrict__ R, float* __restrict__ H)
{
    long i = (long)blockIdx.x * blockDim.x + threadIdx.x;   // one float4 per thread
    int c4 = (int)((i * 4) & 63);
    float4 s = ((const float4*)S)[i];
    float4 r = ((const float4*)R)[i];
    float4 a = *(const float4*)(g_scale + c4);
    float4 b = *(const float4*)(g_shift + c4);
    float4 h;
    h.x = fmaxf(s.x * a.x + b.x, 0.f) + r.x;
    h.y = fmaxf(s.y * a.y + b.y, 0.f) + r.y;
    h.z = fmaxf(s.z * a.z + b.z, 0.f) + r.z;
    h.w = fmaxf(s.w * a.w + b.w, 0.f) + r.w;
    ((float4*)H)[i] = h;
}

// ---------------- launch ----------------
extern "C" void kernel_launch(void* const* d_in, const int* in_sizes, int n_in,
                              void* d_out, int out_size)
{
    const float* x     = (const float*)d_in[0];
    const float* adj   = (const float*)d_in[1];
    const float* w_g0  = (const float*)d_in[2];
    const float* b_g0  = (const float*)d_in[3];
    const float* w_g1  = (const float*)d_in[4];
    const float* b_g1  = (const float*)d_in[5];
    const float* w_g2  = (const float*)d_in[6];
    const float* b_g2  = (const float*)d_in[7];
    const float* gamma = (const float*)d_in[8];
    const float* beta  = (const float*)d_in[9];
    const float* w_r0  = (const float*)d_in[10];
    const float* b_r0  = (const float*)d_in[11];
    const float* w_fc  = (const float*)d_in[12];
    const float* b_fc  = (const float*)d_in[13];
    const float* w_fr  = (const float*)d_in[14];
    const float* b_fr  = (const float*)d_in[15];
    float* out = (float*)d_out;

    float *pt, *ps, *ph, *pr;
    cudaGetSymbolAddress((void**)&pt, g_t);
    cudaGetSymbolAddress((void**)&ps, g_s);
    cudaGetSymbolAddress((void**)&ph, g_h);
    cudaGetSymbolAddress((void**)&pr, g_r);

    const int ROWB = ROWS / 64;                // 4000
    const int N4B = (ROWS * HID / 4) / 256;    // 16000

    // CSR of a_hat (recomputed every launch; tiny, fully deterministic)
    prep_deg<<<NN, 128>>>(adj);
    prep_scan<<<1, 512>>>();
    prep_fill<<<4, 128>>>(adj);

    // input GEMMs: t0 = x@w_g0+b, r0 = x@w_r0+b, out = x@w_fr+b_fr
    gemm_kernel<FIN, HID, false><<<dim3(ROWB, 1), 128>>>(x, w_g0, b_g0, pt);
    gemm_kernel<FIN, HID, false><<<dim3(ROWB, 1), 128>>>(x, w_r0, b_r0, pr);
    gemm_kernel<FIN, OUTF, false><<<dim3(ROWB, 2), 128>>>(x, w_fr, b_fr, out);

    for (int i = 0; i < 3; i++) {
        spmm_stats<<<dim3(4, GG), dim3(16, 16)>>>(pt, ps);
        bn_finalize<<<1, HID>>>(gamma + i * HID, beta + i * HID);
        norm_relu_res<<<N4B, 256>>>(ps, (i == 0) ? pr : ph, ph);
        if (i == 0)
            gemm_kernel<HID, HID, false><<<dim3(ROWB, 1), 128>>>(ph, w_g1, b_g1, pt);
        else if (i == 1)
            gemm_kernel<HID, HID, false><<<dim3(ROWB, 1), 128>>>(ph, w_g2, b_g2, pt);
    }

    // out += h @ w_fc + b_fc
    gemm_kernel<HID, OUTF, true><<<dim3(ROWB, 2), 128>>>(ph, w_fc, b_fc, out);
}

// round 3
// speedup vs baseline: 1.3761x; 1.3761x over previous
#include <cuda_runtime.h>
#include <cstdint>

#define GG 512            // B*T graphs
#define NN 500            // nodes
#define FIN 96
#define HID 64
#define OUTF 96
#define ROWS (GG*NN)      // 256000
#define BN_EPS 1e-5f
#define NNZ_MAX (NN*NN)

// ---------------- scratch (device globals; no allocation allowed) ----------------
__device__ float g_t[(long)ROWS*HID];    // GEMM output / SpMM input
__device__ float g_s[(long)ROWS*HID];    // SpMM output
__device__ float g_h[(long)ROWS*HID];    // layer activations
__device__ float g_r[(long)ROWS*HID];    // layer-0 residual (x @ w_r0 + b_r0)
__device__ float g_dinv[NN];
__device__ int   g_cnt[NN];
__device__ int   g_rowptr[NN+1];
__device__ int   g_cols[NNZ_MAX];
__device__ float g_vals[NNZ_MAX];
__device__ float g_sum[HID];
__device__ float g_sumsq[HID];
__device__ float g_scale[HID];
__device__ float g_shift[HID];

// ---------------- prep: degrees / dinv + per-row nnz counts ----------------
__global__ void prep_deg(const float* __restrict__ adj) {
    int m = blockIdx.x;
    int tid = threadIdx.x;
    float sum = 0.f; int cnt = 0;
    for (int n = tid; n < NN; n += blockDim.x) {
        float a = adj[m*NN + n];
        sum += a;
        cnt += (a != 0.f) ? 1 : 0;
    }
    __shared__ float ssum[4]; __shared__ int scnt[4];
    #pragma unroll
    for (int o = 16; o; o >>= 1) {
        sum += __shfl_down_sync(0xFFFFFFFFu, sum, o);
        cnt += __shfl_down_sync(0xFFFFFFFFu, cnt, o);
    }
    int w = tid >> 5;
    if ((tid & 31) == 0) { ssum[w] = sum; scnt[w] = cnt; }
    __syncthreads();
    if (tid == 0) {
        float s = ssum[0] + ssum[1] + ssum[2] + ssum[3];
        int c = scnt[0] + scnt[1] + scnt[2] + scnt[3];
        g_dinv[m] = rsqrtf(1.f + s);
        g_cnt[m] = c + 1;   // + diagonal
    }
    if (blockIdx.x == 0 && tid < HID) { g_sum[tid] = 0.f; g_sumsq[tid] = 0.f; }
}

// exclusive scan of row counts -> rowptr (single block)
__global__ void prep_scan() {
    __shared__ int sc[512];
    int tid = threadIdx.x;
    sc[tid] = (tid < NN) ? g_cnt[tid] : 0;
    __syncthreads();
    for (int off = 1; off < 512; off <<= 1) {
        int v = (tid >= off) ? sc[tid - off] : 0;
        __syncthreads();
        sc[tid] += v;
        __syncthreads();
    }
    if (tid < NN) g_rowptr[tid + 1] = sc[tid];
    if (tid == 0) g_rowptr[0] = 0;
}

// fill CSR with normalized values (deterministic: one thread per row, ascending cols)
__global__ void prep_fill(const float* __restrict__ adj) {
    int m = blockIdx.x * blockDim.x + threadIdx.x;
    if (m >= NN) return;
    float dm = g_dinv[m];
    int p = g_rowptr[m];
    for (int n = 0; n < NN; n++) {
        if (n == m) {
            g_cols[p] = m;
            g_vals[p] = dm * dm;
            p++;
        } else {
            float a = adj[m*NN + n];
            if (a != 0.f) {
                g_cols[p] = n;
                g_vals[p] = dm * a * g_dinv[n];
                p++;
            }
        }
    }
}

// ---------------- tensor-core GEMM (3xTF32 split, fp32-equivalent accuracy) -------
// C[row,c] = sum_f A[row,f]*B[f,c] + bias[c]   (optional += existing C)
// Block tile 128x64, 256 threads = 8 warps (4 M x 2 N), warp tile 32x32,
// mma.sync.m16n8k8: 2 m-tiles x 4 n-tiles per warp, K chunked by 32.

__device__ __forceinline__ void tf32_split(float x, uint32_t& hi, uint32_t& lo) {
    asm("cvt.rna.tf32.f32 %0, %1;" : "=r"(hi) : "f"(x));
    float r = x - __uint_as_float(hi);
    asm("cvt.rna.tf32.f32 %0, %1;" : "=r"(lo) : "f"(r));
}

__device__ __forceinline__ void mma_tf32(float* c, const uint32_t* a, const uint32_t* b) {
    asm volatile(
        "mma.sync.aligned.m16n8k8.row.col.f32.tf32.tf32.f32 "
        "{%0,%1,%2,%3}, {%4,%5,%6,%7}, {%8,%9}, {%0,%1,%2,%3};\n"
        : "+f"(c[0]), "+f"(c[1]), "+f"(c[2]), "+f"(c[3])
        : "r"(a[0]), "r"(a[1]), "r"(a[2]), "r"(a[3]), "r"(b[0]), "r"(b[1]));
}

template<int K, int C, bool ACCUM>
__global__ __launch_bounds__(256) void gemm_tc(
    const float* __restrict__ A, const float* __restrict__ Bw,
    const float* __restrict__ bias, float* __restrict__ Cout)
{
    __shared__ float As[128][36];   // [row][k], stride 36 -> conflict-free frag reads
    __shared__ float Bs[32][68];    // [k][col], stride 68 (16B-aligned float4 stores)

    const int tid = threadIdx.x;
    const int wid = tid >> 5;
    const int lane = tid & 31;
    const int g  = lane >> 2;       // group id 0..7
    const int t4 = lane & 3;        // 0..3
    const int warp_m = wid >> 1;    // 0..3
    const int warp_n = wid & 1;     // 0..1

    const long row0 = (long)blockIdx.x * 128;
    const int col0 = blockIdx.y * 64;

    float acc[2][4][4];
    #pragma unroll
    for (int mt = 0; mt < 2; mt++)
        #pragma unroll
        for (int nt = 0; nt < 4; nt++)
            #pragma unroll
            for (int q = 0; q < 4; q++) acc[mt][nt][q] = 0.f;

    for (int k0 = 0; k0 < K; k0 += 32) {
        // --- load A tile: 128 rows x 32 k (1024 float4, 4 per thread) ---
        #pragma unroll
        for (int i = 0; i < 4; i++) {
            int idx = tid + i * 256;
            int r = idx >> 3;
            int q = idx & 7;
            float4 v = *(const float4*)(A + (row0 + r) * K + (k0 + q * 4));
            As[r][q*4+0] = v.x; As[r][q*4+1] = v.y;
            As[r][q*4+2] = v.z; As[r][q*4+3] = v.w;
        }
        // --- load B tile: 32 k x 64 cols (512 float4, 2 per thread) ---
        #pragma unroll
        for (int i = 0; i < 2; i++) {
            int idx = tid + i * 256;
            int kk = idx >> 4;
            int q = idx & 15;
            int c = col0 + q * 4;
            float4 v = make_float4(0.f, 0.f, 0.f, 0.f);
            if ((C & 63) == 0 || c < C)
                v = *(const float4*)(Bw + (k0 + kk) * C + c);
            *(float4*)&Bs[kk][q*4] = v;
        }
        __syncthreads();

        #pragma unroll
        for (int kk = 0; kk < 4; kk++) {     // 4 k8-steps per 32-chunk
            uint32_t ahi[2][4], alo[2][4];
            #pragma unroll
            for (int mt = 0; mt < 2; mt++) {
                int r = warp_m * 32 + mt * 16 + g;
                int kc = kk * 8 + t4;
                tf32_split(As[r][kc],        ahi[mt][0], alo[mt][0]);
                tf32_split(As[r + 8][kc],    ahi[mt][1], alo[mt][1]);
                tf32_split(As[r][kc + 4],    ahi[mt][2], alo[mt][2]);
                tf32_split(As[r + 8][kc + 4],ahi[mt][3], alo[mt][3]);
            }
            uint32_t bhi[4][2], blo[4][2];
            #pragma unroll
            for (int nt = 0; nt < 4; nt++) {
                int nb = warp_n * 32 + nt * 8 + g;
                int kr = kk * 8 + t4;
                tf32_split(Bs[kr][nb],     bhi[nt][0], blo[nt][0]);
                tf32_split(Bs[kr + 4][nb], bhi[nt][1], blo[nt][1]);
            }
            #pragma unroll
            for (int mt = 0; mt < 2; mt++)
                #pragma unroll
                for (int nt = 0; nt < 4; nt++) {
                    mma_tf32(acc[mt][nt], ahi[mt], bhi[nt]);
                    mma_tf32(acc[mt][nt], ahi[mt], blo[nt]);
                    mma_tf32(acc[mt][nt], alo[mt], bhi[nt]);
                }
        }
        __syncthreads();
    }

    // --- epilogue: bias (+optional accumulate), float2 stores ---
    #pragma unroll
    for (int mt = 0; mt < 2; mt++) {
        long rowa = row0 + warp_m * 32 + mt * 16 + g;
        long rowb = rowa + 8;
        #pragma unroll
        for (int nt = 0; nt < 4; nt++) {
            int col = col0 + warp_n * 32 + nt * 8 + 2 * t4;
            if ((C & 63) == 0 || col < C) {
                float bx = bias[col];
                float by = bias[col + 1];
                float* d0 = Cout + rowa * C + col;
                float* d1 = Cout + rowb * C + col;
                float2 v0 = make_float2(acc[mt][nt][0] + bx, acc[mt][nt][1] + by);
                float2 v1 = make_float2(acc[mt][nt][2] + bx, acc[mt][nt][3] + by);
                if (ACCUM) {
                    float2 o0 = *(const float2*)d0;
                    float2 o1 = *(const float2*)d1;
                    v0.x += o0.x; v0.y += o0.y;
                    v1.x += o1.x; v1.y += o1.y;
                }
                *(float2*)d0 = v0;
                *(float2*)d1 = v1;
            }
        }
    }
}

// ---------------- SpMM (s = a_hat @ t per graph) + BN stats partials ----------------
__global__ __launch_bounds__(256) void spmm_stats(
    const float* __restrict__ T, float* __restrict__ S)
{
    int g = blockIdx.y;
    int m0 = blockIdx.x * 125;
    int cx = threadIdx.x;
    int c4 = cx * 4;
    int yr = threadIdx.y;
    const float* tg = T + (long)g * NN * HID;
    float* sg = S + (long)g * NN * HID;
    float lsum[4] = {0,0,0,0}, lsq[4] = {0,0,0,0};

    for (int m = m0 + yr; m < m0 + 125; m += 16) {
        int jb = g_rowptr[m], je = g_rowptr[m + 1];
        float4 acc = make_float4(0.f, 0.f, 0.f, 0.f);
        int j = jb;
        for (; j + 1 < je; j += 2) {
            int col0 = g_cols[j];     float w0 = g_vals[j];
            int col1 = g_cols[j + 1]; float w1 = g_vals[j + 1];
            float4 t0 = *(const float4*)(tg + col0 * HID + c4);
            float4 t1 = *(const float4*)(tg + col1 * HID + c4);
            acc.x += w0 * t0.x + w1 * t1.x;
            acc.y += w0 * t0.y + w1 * t1.y;
            acc.z += w0 * t0.z + w1 * t1.z;
            acc.w += w0 * t0.w + w1 * t1.w;
        }
        if (j < je) {
            int col = g_cols[j]; float w = g_vals[j];
            float4 tv = *(const float4*)(tg + col * HID + c4);
            acc.x += w * tv.x; acc.y += w * tv.y;
            acc.z += w * tv.z; acc.w += w * tv.w;
        }
        *(float4*)(sg + m * HID + c4) = acc;
        lsum[0] += acc.x; lsum[1] += acc.y; lsum[2] += acc.z; lsum[3] += acc.w;
        lsq[0] += acc.x * acc.x; lsq[1] += acc.y * acc.y;
        lsq[2] += acc.z * acc.z; lsq[3] += acc.w * acc.w;
    }

    __shared__ float red[16][64];
    #pragma unroll
    for (int k = 0; k < 4; k++) red[yr][c4 + k] = lsum[k];
    __syncthreads();
    for (int off = 8; off >= 1; off >>= 1) {
        if (yr < off)
            #pragma unroll
            for (int k = 0; k < 4; k++) red[yr][c4 + k] += red[yr + off][c4 + k];
        __syncthreads();
    }
    if (yr == 0)
        #pragma unroll
        for (int k = 0; k < 4; k++) atomicAdd(&g_sum[c4 + k], red[0][c4 + k]);
    __syncthreads();
    #pragma unroll
    for (int k = 0; k < 4; k++) red[yr][c4 + k] = lsq[k];
    __syncthreads();
    for (int off = 8; off >= 1; off >>= 1) {
        if (yr < off)
            #pragma unroll
            for (int k = 0; k < 4; k++) red[yr][c4 + k] += red[yr + off][c4 + k];
        __syncthreads();
    }
    if (yr == 0)
        #pragma unroll
        for (int k = 0; k < 4; k++) atomicAdd(&g_sumsq[c4 + k], red[0][c4 + k]);
}

// ---------------- BN finalize ----------------
__global__ void bn_finalize(const float* __restrict__ gamma, const float* __restrict__ beta) {
    int c = threadIdx.x;
    float s = g_sum[c], q = g_sumsq[c];
    const float inv = 1.f / (float)ROWS;
    float mean = s * inv;
    float var = q * inv - mean * mean;
    float rstd = rsqrtf(var + BN_EPS);
    float a = rstd * gamma[c];
    g_scale[c] = a;
    g_shift[c] = beta[c] - mean * a;
    g_sum[c] = 0.f; g_sumsq[c] = 0.f;
}

// ---------------- normalize + relu + residual ----------------
__global__ __launch_bounds__(256) void norm_relu_res(
    const float* __restrict__ S, const float* __restrict__ R, float* __restrict__ H)
{
    long i = (long)blockIdx.x * blockDim.x + threadIdx.x;
    int c4 = (int)((i * 4) & 63);
    float4 s = ((const float4*)S)[i];
    float4 r = ((const float4*)R)[i];
    float4 a = *(const float4*)(g_scale + c4);
    float4 b = *(const float4*)(g_shift + c4);
    float4 h;
    h.x = fmaxf(s.x * a.x + b.x, 0.f) + r.x;
    h.y = fmaxf(s.y * a.y + b.y, 0.f) + r.y;
    h.z = fmaxf(s.z * a.z + b.z, 0.f) + r.z;
    h.w = fmaxf(s.w * a.w + b.w, 0.f) + r.w;
    ((float4*)H)[i] = h;
}

// ---------------- launch ----------------
extern "C" void kernel_launch(void* const* d_in, const int* in_sizes, int n_in,
                              void* d_out, int out_size)
{
    const float* x     = (const float*)d_in[0];
    const float* adj   = (const float*)d_in[1];
    const float* w_g0  = (const float*)d_in[2];
    const float* b_g0  = (const float*)d_in[3];
    const float* w_g1  = (const float*)d_in[4];
    const float* b_g1  = (const float*)d_in[5];
    const float* w_g2  = (const float*)d_in[6];
    const float* b_g2  = (const float*)d_in[7];
    const float* gamma = (const float*)d_in[8];
    const float* beta  = (const float*)d_in[9];
    const float* w_r0  = (const float*)d_in[10];
    const float* b_r0  = (const float*)d_in[11];
    const float* w_fc  = (const float*)d_in[12];
    const float* b_fc  = (const float*)d_in[13];
    const float* w_fr  = (const float*)d_in[14];
    const float* b_fr  = (const float*)d_in[15];
    float* out = (float*)d_out;

    float *pt, *ps, *ph, *pr;
    cudaGetSymbolAddress((void**)&pt, g_t);
    cudaGetSymbolAddress((void**)&ps, g_s);
    cudaGetSymbolAddress((void**)&ph, g_h);
    cudaGetSymbolAddress((void**)&pr, g_r);

    const int ROWB = ROWS / 128;               // 2000
    const int N4B = (ROWS * HID / 4) / 256;    // 16000

    // CSR of a_hat (recomputed every launch; tiny, fully deterministic)
    prep_deg<<<NN, 128>>>(adj);
    prep_scan<<<1, 512>>>();
    prep_fill<<<4, 128>>>(adj);

    // input GEMMs: t0 = x@w_g0+b, r0 = x@w_r0+b, out = x@w_fr+b_fr
    gemm_tc<FIN, HID, false><<<dim3(ROWB, 1), 256>>>(x, w_g0, b_g0, pt);
    gemm_tc<FIN, HID, false><<<dim3(ROWB, 1), 256>>>(x, w_r0, b_r0, pr);
    gemm_tc<FIN, OUTF, false><<<dim3(ROWB, 2), 256>>>(x, w_fr, b_fr, out);

    for (int i = 0; i < 3; i++) {
        spmm_stats<<<dim3(4, GG), dim3(16, 16)>>>(pt, ps);
        bn_finalize<<<1, HID>>>(gamma + i * HID, beta + i * HID);
        norm_relu_res<<<N4B, 256>>>(ps, (i == 0) ? pr : ph, ph);
        if (i == 0)
            gemm_tc<HID, HID, false><<<dim3(ROWB, 1), 256>>>(ph, w_g1, b_g1, pt);
        else if (i == 1)
            gemm_tc<HID, HID, false><<<dim3(ROWB, 1), 256>>>(ph, w_g2, b_g2, pt);
    }

    // out += h @ w_fc + b_fc
    gemm_tc<HID, OUTF, true><<<dim3(ROWB, 2), 256>>>(ph, w_fc, b_fc, out);
}

// round 4
// speedup vs baseline: 1.4458x; 1.0507x over previous
#include <cuda_runtime.h>
#include <cstdint>

#define GG 512            // B*T graphs
#define NN 500            // nodes
#define FIN 96
#define HID 64
#define OUTF 96
#define ROWS (GG*NN)      // 256000
#define BN_EPS 1e-5f
#define NNZ_MAX (NN*NN)

// ---------------- scratch (device globals; no allocation allowed) ----------------
__device__ float g_t[(long)ROWS*HID];    // GEMM output / SpMM input
__device__ float g_s[(long)ROWS*HID];    // SpMM output
__device__ float g_h[(long)ROWS*HID];    // layer activations (residual chain)
__device__ float g_r[(long)ROWS*HID];    // layer-0 residual (x @ w_r0 + b_r0)
__device__ float g_dinv[NN];
__device__ int   g_cnt[NN];
__device__ int   g_rowptr[NN+1];
__device__ int   g_cols[NNZ_MAX];
__device__ float g_vals[NNZ_MAX];
__device__ float g_sum[HID];
__device__ float g_sumsq[HID];
__device__ float g_scale[HID];
__device__ float g_shift[HID];

// ---------------- prep: degrees / dinv + per-row nnz counts ----------------
__global__ void prep_deg(const float* __restrict__ adj) {
    int m = blockIdx.x;
    int tid = threadIdx.x;
    float sum = 0.f; int cnt = 0;
    for (int n = tid; n < NN; n += blockDim.x) {
        float a = adj[m*NN + n];
        sum += a;
        cnt += (a != 0.f) ? 1 : 0;
    }
    __shared__ float ssum[4]; __shared__ int scnt[4];
    #pragma unroll
    for (int o = 16; o; o >>= 1) {
        sum += __shfl_down_sync(0xFFFFFFFFu, sum, o);
        cnt += __shfl_down_sync(0xFFFFFFFFu, cnt, o);
    }
    int w = tid >> 5;
    if ((tid & 31) == 0) { ssum[w] = sum; scnt[w] = cnt; }
    __syncthreads();
    if (tid == 0) {
        float s = ssum[0] + ssum[1] + ssum[2] + ssum[3];
        int c = scnt[0] + scnt[1] + scnt[2] + scnt[3];
        g_dinv[m] = rsqrtf(1.f + s);
        g_cnt[m] = c + 1;   // + diagonal
    }
    if (blockIdx.x == 0 && tid < HID) { g_sum[tid] = 0.f; g_sumsq[tid] = 0.f; }
}

// exclusive scan of row counts -> rowptr (single block)
__global__ void prep_scan() {
    __shared__ int sc[512];
    int tid = threadIdx.x;
    sc[tid] = (tid < NN) ? g_cnt[tid] : 0;
    __syncthreads();
    for (int off = 1; off < 512; off <<= 1) {
        int v = (tid >= off) ? sc[tid - off] : 0;
        __syncthreads();
        sc[tid] += v;
        __syncthreads();
    }
    if (tid < NN) g_rowptr[tid + 1] = sc[tid];
    if (tid == 0) g_rowptr[0] = 0;
}

// fill CSR with normalized values (deterministic: one thread per row, ascending cols)
__global__ void prep_fill(const float* __restrict__ adj) {
    int m = blockIdx.x * blockDim.x + threadIdx.x;
    if (m >= NN) return;
    float dm = g_dinv[m];
    int p = g_rowptr[m];
    for (int n = 0; n < NN; n++) {
        if (n == m) {
            g_cols[p] = m;
            g_vals[p] = dm * dm;
            p++;
        } else {
            float a = adj[m*NN + n];
            if (a != 0.f) {
                g_cols[p] = n;
                g_vals[p] = dm * a * g_dinv[n];
                p++;
            }
        }
    }
}

// ---------------- tensor-core GEMM (3xTF32 split, fp32-equivalent accuracy) -------
// C[row,c] = sum_f A'[row,f]*B[f,c] + bias[c]   (optional += existing C)
// FUSE: A'[row,f] = max(A[row,f]*scale[f]+shift[f], 0) + R[row,f]  (BN+ReLU+residual)
//       optionally written out to Hout.
// Block tile 128x64, 256 threads = 8 warps (4 M x 2 N), warp tile 32x32,
// mma.sync.m16n8k8: 2 m-tiles x 4 n-tiles per warp, K chunked by 32.

__device__ __forceinline__ void tf32_split(float x, uint32_t& hi, uint32_t& lo) {
    asm("cvt.rna.tf32.f32 %0, %1;" : "=r"(hi) : "f"(x));
    float r = x - __uint_as_float(hi);
    asm("cvt.rna.tf32.f32 %0, %1;" : "=r"(lo) : "f"(r));
}

__device__ __forceinline__ void mma_tf32(float* c, const uint32_t* a, const uint32_t* b) {
    asm volatile(
        "mma.sync.aligned.m16n8k8.row.col.f32.tf32.tf32.f32 "
        "{%0,%1,%2,%3}, {%4,%5,%6,%7}, {%8,%9}, {%0,%1,%2,%3};\n"
        : "+f"(c[0]), "+f"(c[1]), "+f"(c[2]), "+f"(c[3])
        : "r"(a[0]), "r"(a[1]), "r"(a[2]), "r"(a[3]), "r"(b[0]), "r"(b[1]));
}

template<int K, int C, bool ACCUM, bool FUSE, bool WRITE_H>
__global__ __launch_bounds__(256) void gemm_tc(
    const float* __restrict__ A, const float* __restrict__ R, float* __restrict__ Hout,
    const float* __restrict__ Bw, const float* __restrict__ bias, float* __restrict__ Cout)
{
    __shared__ float As[128][36];   // [row][k], stride 36 -> conflict-free frag reads
    __shared__ float Bs[32][68];    // [k][col], stride 68 (16B-aligned float4 stores)
    __shared__ float s_scale[HID], s_shift[HID];

    const int tid = threadIdx.x;
    const int wid = tid >> 5;
    const int lane = tid & 31;
    const int g  = lane >> 2;       // group id 0..7
    const int t4 = lane & 3;        // 0..3
    const int warp_m = wid >> 1;    // 0..3
    const int warp_n = wid & 1;     // 0..1

    const long row0 = (long)blockIdx.x * 128;
    const int col0 = blockIdx.y * 64;

    if (FUSE) {
        if (tid < HID) s_scale[tid] = g_scale[tid];
        else if (tid < 2*HID) s_shift[tid - HID] = g_shift[tid - HID];
        __syncthreads();
    }

    float acc[2][4][4];
    #pragma unroll
    for (int mt = 0; mt < 2; mt++)
        #pragma unroll
        for (int nt = 0; nt < 4; nt++)
            #pragma unroll
            for (int q = 0; q < 4; q++) acc[mt][nt][q] = 0.f;

    for (int k0 = 0; k0 < K; k0 += 32) {
        // --- load A tile: 128 rows x 32 k (1024 float4, 4 per thread) ---
        #pragma unroll
        for (int i = 0; i < 4; i++) {
            int idx = tid + i * 256;
            int r = idx >> 3;
            int q = idx & 7;
            long off = (row0 + r) * K + (k0 + q * 4);
            float4 v = *(const float4*)(A + off);
            if (FUSE) {
                int kc = k0 + q * 4;
                float4 rv = *(const float4*)(R + off);
                v.x = fmaxf(v.x * s_scale[kc+0] + s_shift[kc+0], 0.f) + rv.x;
                v.y = fmaxf(v.y * s_scale[kc+1] + s_shift[kc+1], 0.f) + rv.y;
                v.z = fmaxf(v.z * s_scale[kc+2] + s_shift[kc+2], 0.f) + rv.z;
                v.w = fmaxf(v.w * s_scale[kc+3] + s_shift[kc+3], 0.f) + rv.w;
                if (WRITE_H) *(float4*)(Hout + off) = v;
            }
            As[r][q*4+0] = v.x; As[r][q*4+1] = v.y;
            As[r][q*4+2] = v.z; As[r][q*4+3] = v.w;
        }
        // --- load B tile: 32 k x 64 cols (512 float4, 2 per thread) ---
        #pragma unroll
        for (int i = 0; i < 2; i++) {
            int idx = tid + i * 256;
            int kk = idx >> 4;
            int q = idx & 15;
            int c = col0 + q * 4;
            float4 v = make_float4(0.f, 0.f, 0.f, 0.f);
            if ((C & 63) == 0 || c < C)
                v = *(const float4*)(Bw + (k0 + kk) * C + c);
            *(float4*)&Bs[kk][q*4] = v;
        }
        __syncthreads();

        #pragma unroll
        for (int kk = 0; kk < 4; kk++) {     // 4 k8-steps per 32-chunk
            uint32_t ahi[2][4], alo[2][4];
            #pragma unroll
            for (int mt = 0; mt < 2; mt++) {
                int r = warp_m * 32 + mt * 16 + g;
                int kc = kk * 8 + t4;
                tf32_split(As[r][kc],        ahi[mt][0], alo[mt][0]);
                tf32_split(As[r + 8][kc],    ahi[mt][1], alo[mt][1]);
                tf32_split(As[r][kc + 4],    ahi[mt][2], alo[mt][2]);
                tf32_split(As[r + 8][kc + 4],ahi[mt][3], alo[mt][3]);
            }
            uint32_t bhi[4][2], blo[4][2];
            #pragma unroll
            for (int nt = 0; nt < 4; nt++) {
                int nb = warp_n * 32 + nt * 8 + g;
                int kr = kk * 8 + t4;
                tf32_split(Bs[kr][nb],     bhi[nt][0], blo[nt][0]);
                tf32_split(Bs[kr + 4][nb], bhi[nt][1], blo[nt][1]);
            }
            #pragma unroll
            for (int mt = 0; mt < 2; mt++)
                #pragma unroll
                for (int nt = 0; nt < 4; nt++) {
                    mma_tf32(acc[mt][nt], ahi[mt], bhi[nt]);
                    mma_tf32(acc[mt][nt], ahi[mt], blo[nt]);
                    mma_tf32(acc[mt][nt], alo[mt], bhi[nt]);
                }
        }
        __syncthreads();
    }

    // --- epilogue: bias (+optional accumulate), float2 stores ---
    #pragma unroll
    for (int mt = 0; mt < 2; mt++) {
        long rowa = row0 + warp_m * 32 + mt * 16 + g;
        long rowb = rowa + 8;
        #pragma unroll
        for (int nt = 0; nt < 4; nt++) {
            int col = col0 + warp_n * 32 + nt * 8 + 2 * t4;
            if ((C & 63) == 0 || col < C) {
                float bx = bias[col];
                float by = bias[col + 1];
                float* d0 = Cout + rowa * C + col;
                float* d1 = Cout + rowb * C + col;
                float2 v0 = make_float2(acc[mt][nt][0] + bx, acc[mt][nt][1] + by);
                float2 v1 = make_float2(acc[mt][nt][2] + bx, acc[mt][nt][3] + by);
                if (ACCUM) {
                    float2 o0 = *(const float2*)d0;
                    float2 o1 = *(const float2*)d1;
                    v0.x += o0.x; v0.y += o0.y;
                    v1.x += o1.x; v1.y += o1.y;
                }
                *(float2*)d0 = v0;
                *(float2*)d1 = v1;
            }
        }
    }
}

// ---------------- SpMM (s = a_hat @ t per graph) + BN stats partials ----------------
// Unroll-4 gathers with dual accumulators for MLP.
__global__ __launch_bounds__(256) void spmm_stats(
    const float* __restrict__ T, float* __restrict__ S)
{
    int g = blockIdx.y;
    int m0 = blockIdx.x * 125;
    int cx = threadIdx.x;
    int c4 = cx * 4;
    int yr = threadIdx.y;
    const float* tg = T + (long)g * NN * HID;
    float* sg = S + (long)g * NN * HID;
    float lsum[4] = {0,0,0,0}, lsq[4] = {0,0,0,0};

    for (int m = m0 + yr; m < m0 + 125; m += 16) {
        int jb = g_rowptr[m], je = g_rowptr[m + 1];
        float4 a0 = make_float4(0.f, 0.f, 0.f, 0.f);
        float4 a1 = make_float4(0.f, 0.f, 0.f, 0.f);
        int j = jb;
        for (; j + 3 < je; j += 4) {
            int   c0 = g_cols[j],     c1 = g_cols[j + 1];
            int   c2 = g_cols[j + 2], c3 = g_cols[j + 3];
            float w0 = g_vals[j],     w1 = g_vals[j + 1];
            float w2 = g_vals[j + 2], w3 = g_vals[j + 3];
            float4 t0 = *(const float4*)(tg + c0 * HID + c4);
            float4 t1 = *(const float4*)(tg + c1 * HID + c4);
            float4 t2 = *(const float4*)(tg + c2 * HID + c4);
            float4 t3 = *(const float4*)(tg + c3 * HID + c4);
            a0.x += w0 * t0.x + w1 * t1.x;  a1.x += w2 * t2.x + w3 * t3.x;
            a0.y += w0 * t0.y + w1 * t1.y;  a1.y += w2 * t2.y + w3 * t3.y;
            a0.z += w0 * t0.z + w1 * t1.z;  a1.z += w2 * t2.z + w3 * t3.z;
            a0.w += w0 * t0.w + w1 * t1.w;  a1.w += w2 * t2.w + w3 * t3.w;
        }
        for (; j < je; j++) {
            int col = g_cols[j]; float w = g_vals[j];
            float4 tv = *(const float4*)(tg + col * HID + c4);
            a0.x += w * tv.x; a0.y += w * tv.y;
            a0.z += w * tv.z; a0.w += w * tv.w;
        }
        float4 acc = make_float4(a0.x + a1.x, a0.y + a1.y, a0.z + a1.z, a0.w + a1.w);
        *(float4*)(sg + m * HID + c4) = acc;
        lsum[0] += acc.x; lsum[1] += acc.y; lsum[2] += acc.z; lsum[3] += acc.w;
        lsq[0] += acc.x * acc.x; lsq[1] += acc.y * acc.y;
        lsq[2] += acc.z * acc.z; lsq[3] += acc.w * acc.w;
    }

    __shared__ float red[16][64];
    #pragma unroll
    for (int k = 0; k < 4; k++) red[yr][c4 + k] = lsum[k];
    __syncthreads();
    for (int off = 8; off >= 1; off >>= 1) {
        if (yr < off)
            #pragma unroll
            for (int k = 0; k < 4; k++) red[yr][c4 + k] += red[yr + off][c4 + k];
        __syncthreads();
    }
    if (yr == 0)
        #pragma unroll
        for (int k = 0; k < 4; k++) atomicAdd(&g_sum[c4 + k], red[0][c4 + k]);
    __syncthreads();
    #pragma unroll
    for (int k = 0; k < 4; k++) red[yr][c4 + k] = lsq[k];
    __syncthreads();
    for (int off = 8; off >= 1; off >>= 1) {
        if (yr < off)
            #pragma unroll
            for (int k = 0; k < 4; k++) red[yr][c4 + k] += red[yr + off][c4 + k];
        __syncthreads();
    }
    if (yr == 0)
        #pragma unroll
        for (int k = 0; k < 4; k++) atomicAdd(&g_sumsq[c4 + k], red[0][c4 + k]);
}

// ---------------- BN finalize ----------------
__global__ void bn_finalize(const float* __restrict__ gamma, const float* __restrict__ beta) {
    int c = threadIdx.x;
    float s = g_sum[c], q = g_sumsq[c];
    const float inv = 1.f / (float)ROWS;
    float mean = s * inv;
    float var = q * inv - mean * mean;
    float rstd = rsqrtf(var + BN_EPS);
    float a = rstd * gamma[c];
    g_scale[c] = a;
    g_shift[c] = beta[c] - mean * a;
    g_sum[c] = 0.f; g_sumsq[c] = 0.f;
}

// ---------------- launch ----------------
extern "C" void kernel_launch(void* const* d_in, const int* in_sizes, int n_in,
                              void* d_out, int out_size)
{
    const float* x     = (const float*)d_in[0];
    const float* adj   = (const float*)d_in[1];
    const float* w_g0  = (const float*)d_in[2];
    const float* b_g0  = (const float*)d_in[3];
    const float* w_g1  = (const float*)d_in[4];
    const float* b_g1  = (const float*)d_in[5];
    const float* w_g2  = (const float*)d_in[6];
    const float* b_g2  = (const float*)d_in[7];
    const float* gamma = (const float*)d_in[8];
    const float* beta  = (const float*)d_in[9];
    const float* w_r0  = (const float*)d_in[10];
    const float* b_r0  = (const float*)d_in[11];
    const float* w_fc  = (const float*)d_in[12];
    const float* b_fc  = (const float*)d_in[13];
    const float* w_fr  = (const float*)d_in[14];
    const float* b_fr  = (const float*)d_in[15];
    float* out = (float*)d_out;

    float *pt, *ps, *ph, *pr;
    cudaGetSymbolAddress((void**)&pt, g_t);
    cudaGetSymbolAddress((void**)&ps, g_s);
    cudaGetSymbolAddress((void**)&ph, g_h);
    cudaGetSymbolAddress((void**)&pr, g_r);

    const int ROWB = ROWS / 128;               // 2000

    // CSR of a_hat (recomputed every launch; tiny, fully deterministic)
    prep_deg<<<NN, 128>>>(adj);
    prep_scan<<<1, 512>>>();
    prep_fill<<<4, 128>>>(adj);

    // input GEMMs: t0 = x@w_g0+b, r0 = x@w_r0+b, out = x@w_fr+b_fr
    gemm_tc<FIN, HID, false, false, false><<<dim3(ROWB, 1), 256>>>(x, nullptr, nullptr, w_g0, b_g0, pt);
    gemm_tc<FIN, HID, false, false, false><<<dim3(ROWB, 1), 256>>>(x, nullptr, nullptr, w_r0, b_r0, pr);
    gemm_tc<FIN, OUTF, false, false, false><<<dim3(ROWB, 2), 256>>>(x, nullptr, nullptr, w_fr, b_fr, out);

    // layer 0: s = a_hat @ t0; h0 = relu(bn(s)) + r0; t1 = h0 @ w_g1 + b
    spmm_stats<<<dim3(4, GG), dim3(16, 16)>>>(pt, ps);
    bn_finalize<<<1, HID>>>(gamma + 0 * HID, beta + 0 * HID);
    gemm_tc<HID, HID, false, true, true><<<dim3(ROWB, 1), 256>>>(ps, pr, ph, w_g1, b_g1, pt);

    // layer 1: s = a_hat @ t1; h1 = relu(bn(s)) + h0; t2 = h1 @ w_g2 + b
    spmm_stats<<<dim3(4, GG), dim3(16, 16)>>>(pt, ps);
    bn_finalize<<<1, HID>>>(gamma + 1 * HID, beta + 1 * HID);
    gemm_tc<HID, HID, false, true, true><<<dim3(ROWB, 1), 256>>>(ps, ph, ph, w_g2, b_g2, pt);

    // layer 2: s = a_hat @ t2; h2 = relu(bn(s)) + h1 (never materialized);
    //          out += h2 @ w_fc + b_fc
    spmm_stats<<<dim3(4, GG), dim3(16, 16)>>>(pt, ps);
    bn_finalize<<<1, HID>>>(gamma + 2 * HID, beta + 2 * HID);
    gemm_tc<HID, OUTF, true, true, false><<<dim3(ROWB, 2), 256>>>(ps, ph, nullptr, w_fc, b_fc, out);
}